// round 9
// baseline (speedup 1.0000x reference)
#include <cuda_runtime.h>
#include <cuda_bf16.h>
#include <math.h>
#include <stdint.h>

// ================= device scratch (allocation-free) =================
__device__ __nv_bfloat16 g_KVh [7864320], g_KVl [7864320];
__device__ __nv_bfloat16 g_Wkh [7372800], g_Wkl [7372800];
__device__ __nv_bfloat16 g_Wvh [7372800], g_Wvl [7372800];
__device__ __nv_bfloat16 g_Qh  [7864320], g_Ql  [7864320];
__device__ __nv_bfloat16 g_Wqh [2785280], g_Wql [2785280];
__device__ __nv_bfloat16 g_Woh [348160],  g_Wol [348160];
__device__ __nv_bfloat16 g_Kth [7864320], g_Ktl [7864320];   // Kt, then reused as KVtT
__device__ __nv_bfloat16 g_KVth[7864320], g_KVtl[7864320];
__device__ __nv_bfloat16 g_QtTh[4194304], g_QtTl[4194304];
__device__ __nv_bfloat16 g_Ph [31457280], g_Pl [31457280];
__device__ __nv_bfloat16 g_Oh [4194304],  g_Ol [4194304];
__device__ float g_S[31457280];
__device__ float g_part[8192];
__device__ float g_stats[128];

// ================= helpers =================
__device__ __forceinline__ void mma_bf16(float* c, const uint32_t* a, const uint32_t* b)
{
    asm volatile(
        "mma.sync.aligned.m16n8k16.row.col.f32.bf16.bf16.f32 "
        "{%0,%1,%2,%3}, {%4,%5,%6,%7}, {%8,%9}, {%0,%1,%2,%3};"
        : "+f"(c[0]), "+f"(c[1]), "+f"(c[2]), "+f"(c[3])
        : "r"(a[0]), "r"(a[1]), "r"(a[2]), "r"(a[3]), "r"(b[0]), "r"(b[1]));
}

__device__ __forceinline__ void cp16(void* s, const void* g)
{
    uint32_t sa = (uint32_t)__cvta_generic_to_shared(s);
    asm volatile("cp.async.cg.shared.global [%0], [%1], 16;" :: "r"(sa), "l"(g));
}

__device__ __forceinline__ void split2(float x, float y, __nv_bfloat162& h, __nv_bfloat162& l)
{
    h.x = __float2bfloat16(x); h.y = __float2bfloat16(y);
    l.x = __float2bfloat16(x - __bfloat162float(h.x));
    l.y = __float2bfloat16(y - __bfloat162float(h.y));
}

// ================= convert: fp32 -> bf16 hi/lo =================
__global__ void cvt_split(const float* __restrict__ x, __nv_bfloat16* __restrict__ h,
                          __nv_bfloat16* __restrict__ l, int n4)
{
    int i = blockIdx.x * 256 + threadIdx.x;
    if (i >= n4) return;
    float4 v = reinterpret_cast<const float4*>(x)[i];
    __nv_bfloat162 h0, l0, h1, l1;
    split2(v.x, v.y, h0, l0);
    split2(v.z, v.w, h1, l1);
    reinterpret_cast<__nv_bfloat162*>(h)[2*i]   = h0;
    reinterpret_cast<__nv_bfloat162*>(h)[2*i+1] = h1;
    reinterpret_cast<__nv_bfloat162*>(l)[2*i]   = l0;
    reinterpret_cast<__nv_bfloat162*>(l)[2*i+1] = l1;
}

// ================= GEMM: C[m,n] = alpha * sum_k A[m,k]*B[n,k], bf16 hi/lo inputs
// MODE 0: fp32 C   MODE 1: bf16 hi/lo C   MODE 2: fp32 C + per-block (sum,sumsq) partials
template<int BM, int MODE>
__global__ void __launch_bounds__(128)
gemm_bf(const __nv_bfloat16* __restrict__ Agh, const __nv_bfloat16* __restrict__ Agl,
        const __nv_bfloat16* __restrict__ Bgh, const __nv_bfloat16* __restrict__ Bgl,
        float* __restrict__ C, __nv_bfloat16* __restrict__ Ch, __nv_bfloat16* __restrict__ Cl,
        float* __restrict__ part,
        int K, int lda, int ldb, int ldc,
        long aS, int aMask, long bS, int bMask, long cS, float alpha)
{
    constexpr int BK = 32, LDT = BK + 8;
    constexpr int MT = BM / 32;
    extern __shared__ __align__(16) char dsm[];
    __nv_bfloat16* sA = reinterpret_cast<__nv_bfloat16*>(dsm);   // [2buf][2hl][BM][LDT]
    __nv_bfloat16* sB = sA + 4 * BM * LDT;                       // [2buf][2hl][64][LDT]

    const int z = blockIdx.z;
    Agh += (long)(z & aMask) * aS;  Agl += (long)(z & aMask) * aS;
    Bgh += (long)(z & bMask) * bS;  Bgl += (long)(z & bMask) * bS;
    if (MODE == 1) { Ch += (long)z * cS; Cl += (long)z * cS; }
    else           { C  += (long)z * cS; }

    const int m0 = blockIdx.y * BM, n0 = blockIdx.x * 64;
    const int tid = threadIdx.x, lane = tid & 31, warp = tid >> 5;
    const int wy = warp >> 1, wx = warp & 1;        // 2x2 warps
    const int m0w = wy * (BM / 2), n0w = wx * 32;
    const int r = lane >> 2, p = lane & 3;

    float acc[MT][4][4];
#pragma unroll
    for (int mt = 0; mt < MT; mt++)
#pragma unroll
        for (int nt = 0; nt < 4; nt++)
#pragma unroll
            for (int i = 0; i < 4; i++) acc[mt][nt][i] = 0.f;

    const int T = K / BK;

    auto stage = [&](int t, int s) {
        const int k0 = t * BK;
#pragma unroll
        for (int it = 0; it < BM / 32; it++) {
            int idx = tid + it * 128;
            int c = idx & 3, m = idx >> 2;
            long off = (long)(m0 + m) * lda + k0 + c * 8;
            cp16(sA + ((s * 2 + 0) * BM + m) * LDT + c * 8, Agh + off);
            cp16(sA + ((s * 2 + 1) * BM + m) * LDT + c * 8, Agl + off);
        }
#pragma unroll
        for (int it = 0; it < 2; it++) {
            int idx = tid + it * 128;
            int c = idx & 3, n = idx >> 2;
            long off = (long)(n0 + n) * ldb + k0 + c * 8;
            cp16(sB + ((s * 2 + 0) * 64 + n) * LDT + c * 8, Bgh + off);
            cp16(sB + ((s * 2 + 1) * 64 + n) * LDT + c * 8, Bgl + off);
        }
        asm volatile("cp.async.commit_group;");
    };

    stage(0, 0);
    int buf = 0;
    for (int t = 0; t < T; t++) {
        if (t + 1 < T) { stage(t + 1, buf ^ 1); asm volatile("cp.async.wait_group 1;"); }
        else           { asm volatile("cp.async.wait_group 0;"); }
        __syncthreads();
#pragma unroll
        for (int ks = 0; ks < 2; ks++) {
            const int kb = ks * 16 + 2 * p;
            uint32_t ah[MT][4], al[MT][4], bh[4][2], bl[4][2];
#pragma unroll
            for (int mt = 0; mt < MT; mt++) {
                int row = m0w + mt * 16 + r;
                const __nv_bfloat16* ph = sA + ((buf * 2 + 0) * BM + row) * LDT + kb;
                const __nv_bfloat16* pl = sA + ((buf * 2 + 1) * BM + row) * LDT + kb;
                ah[mt][0] = *(const uint32_t*)(ph);
                ah[mt][1] = *(const uint32_t*)(ph + 8 * LDT);
                ah[mt][2] = *(const uint32_t*)(ph + 8);
                ah[mt][3] = *(const uint32_t*)(ph + 8 * LDT + 8);
                al[mt][0] = *(const uint32_t*)(pl);
                al[mt][1] = *(const uint32_t*)(pl + 8 * LDT);
                al[mt][2] = *(const uint32_t*)(pl + 8);
                al[mt][3] = *(const uint32_t*)(pl + 8 * LDT + 8);
            }
#pragma unroll
            for (int nt = 0; nt < 4; nt++) {
                int row = n0w + nt * 8 + r;
                const __nv_bfloat16* ph = sB + ((buf * 2 + 0) * 64 + row) * LDT + kb;
                const __nv_bfloat16* pl = sB + ((buf * 2 + 1) * 64 + row) * LDT + kb;
                bh[nt][0] = *(const uint32_t*)(ph);
                bh[nt][1] = *(const uint32_t*)(ph + 8);
                bl[nt][0] = *(const uint32_t*)(pl);
                bl[nt][1] = *(const uint32_t*)(pl + 8);
            }
#pragma unroll
            for (int mt = 0; mt < MT; mt++)
#pragma unroll
                for (int nt = 0; nt < 4; nt++) {
                    mma_bf16(acc[mt][nt], ah[mt], bh[nt]);  // hi*hi
                    mma_bf16(acc[mt][nt], ah[mt], bl[nt]);  // hi*lo
                    mma_bf16(acc[mt][nt], al[mt], bh[nt]);  // lo*hi
                }
        }
        __syncthreads();
        buf ^= 1;
    }

    // ---------------- epilogue ----------------
    float sum = 0.f, ss = 0.f;
#pragma unroll
    for (int mt = 0; mt < MT; mt++) {
        int row = m0 + m0w + mt * 16 + r;
#pragma unroll
        for (int nt = 0; nt < 4; nt++) {
            int col = n0 + n0w + nt * 8 + 2 * p;
            float x0 = alpha * acc[mt][nt][0], y0 = alpha * acc[mt][nt][1];
            float x1 = alpha * acc[mt][nt][2], y1 = alpha * acc[mt][nt][3];
            if (MODE == 1) {
                __nv_bfloat162 h, l;
                split2(x0, y0, h, l);
                *reinterpret_cast<__nv_bfloat162*>(Ch + (long)row * ldc + col) = h;
                *reinterpret_cast<__nv_bfloat162*>(Cl + (long)row * ldc + col) = l;
                split2(x1, y1, h, l);
                *reinterpret_cast<__nv_bfloat162*>(Ch + (long)(row + 8) * ldc + col) = h;
                *reinterpret_cast<__nv_bfloat162*>(Cl + (long)(row + 8) * ldc + col) = l;
            } else {
                float2 v0 = make_float2(x0, y0), v1 = make_float2(x1, y1);
                *reinterpret_cast<float2*>(C + (long)row * ldc + col)       = v0;
                *reinterpret_cast<float2*>(C + (long)(row + 8) * ldc + col) = v1;
                if (MODE == 2) {
                    sum += x0 + y0 + x1 + y1;
                    ss  += x0*x0 + y0*y0 + x1*x1 + y1*y1;
                }
            }
        }
    }
    if (MODE == 2) {
#pragma unroll
        for (int o = 16; o; o >>= 1) {
            sum += __shfl_xor_sync(0xffffffffu, sum, o);
            ss  += __shfl_xor_sync(0xffffffffu, ss, o);
        }
        float* red = reinterpret_cast<float*>(dsm);
        if (lane == 0) { red[warp] = sum; red[4 + warp] = ss; }
        __syncthreads();
        if (tid == 0) {
            float s1 = red[0] + red[1] + red[2] + red[3];
            float s2 = red[4] + red[5] + red[6] + red[7];
            int bz = blockIdx.y * gridDim.x + blockIdx.x;
            part[((long)z * 64 + bz) * 2 + 0] = s1;
            part[((long)z * 64 + bz) * 2 + 1] = s2;
        }
    }
}

// ================= stats finalize (deterministic) =================
__global__ void stats_fin(const float* __restrict__ part, float* __restrict__ stats,
                          int nblocks, float invElems)
{
    int z = blockIdx.x, tid = threadIdx.x;
    __shared__ float s1[64], s2[64];
    float a = 0.f, b = 0.f;
    for (int i = tid; i < nblocks; i += 64) {
        a += part[((long)z * 64 + i) * 2 + 0];
        b += part[((long)z * 64 + i) * 2 + 1];
    }
    s1[tid] = a; s2[tid] = b; __syncthreads();
    for (int o = 32; o; o >>= 1) {
        if (tid < o) { s1[tid] += s1[tid + o]; s2[tid] += s2[tid + o]; }
        __syncthreads();
    }
    if (tid == 0) {
        float m = s1[0] * invElems;
        float v = s2[0] * invElems - m * m;
        stats[2 * z]     = m;
        stats[2 * z + 1] = rsqrtf(v + 1e-5f);
    }
}

// ================= inorm apply + softmax over 960, bf16 hi/lo out =================
__global__ void inorm_softmax_bf(const float* __restrict__ S, const float* __restrict__ stats,
                                 __nv_bfloat16* __restrict__ Ph, __nv_bfloat16* __restrict__ Pl,
                                 int rowsPerBatch)
{
    const int row = blockIdx.x;
    const int bh = row / rowsPerBatch;
    const float* p = S + (long)row * 960;
    const int tid = threadIdx.x;
    const bool act = tid < 240;
    const float mean = stats[2 * bh], rstd = stats[2 * bh + 1];

    float4 v = make_float4(0.f, 0.f, 0.f, 0.f);
    if (act) v = *reinterpret_cast<const float4*>(&p[tid * 4]);
    v.x = (v.x - mean) * rstd; v.y = (v.y - mean) * rstd;
    v.z = (v.z - mean) * rstd; v.w = (v.w - mean) * rstd;

    __shared__ float sh[256];
    float mx = act ? fmaxf(fmaxf(v.x, v.y), fmaxf(v.z, v.w)) : -1e30f;
    sh[tid] = mx; __syncthreads();
    for (int o = 128; o > 0; o >>= 1) {
        if (tid < o) sh[tid] = fmaxf(sh[tid], sh[tid + o]);
        __syncthreads();
    }
    mx = sh[0]; __syncthreads();

    float4 e;
    e.x = __expf(v.x - mx); e.y = __expf(v.y - mx);
    e.z = __expf(v.z - mx); e.w = __expf(v.w - mx);
    float s = act ? (e.x + e.y + e.z + e.w) : 0.f;
    sh[tid] = s; __syncthreads();
    for (int o = 128; o > 0; o >>= 1) {
        if (tid < o) sh[tid] += sh[tid + o];
        __syncthreads();
    }
    const float inv = 1.f / sh[0];
    if (act) {
        e.x *= inv; e.y *= inv; e.z *= inv; e.w *= inv;
        long off = (long)row * 960 + tid * 4;
        __nv_bfloat162 h, l;
        split2(e.x, e.y, h, l);
        *reinterpret_cast<__nv_bfloat162*>(Ph + off)     = h;
        *reinterpret_cast<__nv_bfloat162*>(Pl + off)     = l;
        split2(e.z, e.w, h, l);
        *reinterpret_cast<__nv_bfloat162*>(Ph + off + 2) = h;
        *reinterpret_cast<__nv_bfloat162*>(Pl + off + 2) = l;
    }
}

// ================= transpose bf16 pair: [z][128][960] -> [z][960][128] =================
__global__ void transpose_bf(const __nv_bfloat16* __restrict__ ih, const __nv_bfloat16* __restrict__ il,
                             __nv_bfloat16* __restrict__ oh, __nv_bfloat16* __restrict__ ol)
{
    __shared__ __nv_bfloat16 th[32][33], tl[32][33];
    const int b = blockIdx.z;
    const int s0 = blockIdx.x * 32, n0 = blockIdx.y * 32;
    ih += (long)b * 128 * 960; il += (long)b * 128 * 960;
    oh += (long)b * 960 * 128; ol += (long)b * 960 * 128;
    const int tx = threadIdx.x, ty = threadIdx.y;
#pragma unroll
    for (int i = 0; i < 4; i++) {
        th[ty + 8 * i][tx] = ih[(long)(n0 + ty + 8 * i) * 960 + s0 + tx];
        tl[ty + 8 * i][tx] = il[(long)(n0 + ty + 8 * i) * 960 + s0 + tx];
    }
    __syncthreads();
#pragma unroll
    for (int i = 0; i < 4; i++) {
        oh[(long)(s0 + ty + 8 * i) * 128 + n0 + tx] = th[tx][ty + 8 * i];
        ol[(long)(s0 + ty + 8 * i) * 128 + n0 + tx] = tl[tx][ty + 8 * i];
    }
}

// ================= host-side dispatch =================
static inline void run_gemm(int BM, int MODE, dim3 grid,
    const __nv_bfloat16* Ah, const __nv_bfloat16* Al,
    const __nv_bfloat16* Bh, const __nv_bfloat16* Bl,
    float* C, __nv_bfloat16* Ch, __nv_bfloat16* Cl, float* part,
    int K, int lda, int ldb, int ldc,
    long aS, int aMask, long bS, int bMask, long cS, float alpha)
{
    if (BM == 128) {
        size_t sm = (size_t)(4 * 128 * 40 + 4 * 64 * 40) * 2;   // 61440 B
        if (MODE == 0) {
            cudaFuncSetAttribute(gemm_bf<128,0>, cudaFuncAttributeMaxDynamicSharedMemorySize, (int)sm);
            gemm_bf<128,0><<<grid,128,sm>>>(Ah,Al,Bh,Bl,C,Ch,Cl,part,K,lda,ldb,ldc,aS,aMask,bS,bMask,cS,alpha);
        } else if (MODE == 1) {
            cudaFuncSetAttribute(gemm_bf<128,1>, cudaFuncAttributeMaxDynamicSharedMemorySize, (int)sm);
            gemm_bf<128,1><<<grid,128,sm>>>(Ah,Al,Bh,Bl,C,Ch,Cl,part,K,lda,ldb,ldc,aS,aMask,bS,bMask,cS,alpha);
        } else {
            cudaFuncSetAttribute(gemm_bf<128,2>, cudaFuncAttributeMaxDynamicSharedMemorySize, (int)sm);
            gemm_bf<128,2><<<grid,128,sm>>>(Ah,Al,Bh,Bl,C,Ch,Cl,part,K,lda,ldb,ldc,aS,aMask,bS,bMask,cS,alpha);
        }
    } else {
        size_t sm = (size_t)(4 * 64 * 40 + 4 * 64 * 40) * 2;    // 40960 B (< 48K default)
        if (MODE == 1) {
            gemm_bf<64,1><<<grid,128,sm>>>(Ah,Al,Bh,Bl,C,Ch,Cl,part,K,lda,ldb,ldc,aS,aMask,bS,bMask,cS,alpha);
        } else {
            gemm_bf<64,2><<<grid,128,sm>>>(Ah,Al,Bh,Bl,C,Ch,Cl,part,K,lda,ldb,ldc,aS,aMask,bS,bMask,cS,alpha);
        }
    }
}

static inline void cvt(const float* x, __nv_bfloat16* h, __nv_bfloat16* l, long n)
{
    int n4 = (int)(n / 4);
    cvt_split<<<(n4 + 255) / 256, 256>>>(x, h, l, n4);
}

extern "C" void kernel_launch(void* const* d_in, const int* in_sizes, int n_in,
                              void* d_out, int out_size)
{
    const float* Q[4]  = {(const float*)d_in[0], (const float*)d_in[1],
                          (const float*)d_in[2], (const float*)d_in[3]};
    const float* KV    = (const float*)d_in[4];
    const float* Wk    = (const float*)d_in[5];
    const float* Wv    = (const float*)d_in[6];
    const float* Wq[4] = {(const float*)d_in[7], (const float*)d_in[8],
                          (const float*)d_in[9], (const float*)d_in[10]};
    const float* Wo[4] = {(const float*)d_in[11], (const float*)d_in[12],
                          (const float*)d_in[13], (const float*)d_in[14]};
    float* out = (float*)d_out;

    __nv_bfloat16 *KVh,*KVl,*Wkh,*Wkl,*Wvh,*Wvl,*Qh,*Ql,*Wqh,*Wql,*Woh,*Wol;
    __nv_bfloat16 *Kth,*Ktl,*KVth,*KVtl,*QtTh,*QtTl,*Ph,*Pl,*Oh,*Ol;
    float *S, *part, *stats;
    cudaGetSymbolAddress((void**)&KVh, g_KVh);   cudaGetSymbolAddress((void**)&KVl, g_KVl);
    cudaGetSymbolAddress((void**)&Wkh, g_Wkh);   cudaGetSymbolAddress((void**)&Wkl, g_Wkl);
    cudaGetSymbolAddress((void**)&Wvh, g_Wvh);   cudaGetSymbolAddress((void**)&Wvl, g_Wvl);
    cudaGetSymbolAddress((void**)&Qh,  g_Qh);    cudaGetSymbolAddress((void**)&Ql,  g_Ql);
    cudaGetSymbolAddress((void**)&Wqh, g_Wqh);   cudaGetSymbolAddress((void**)&Wql, g_Wql);
    cudaGetSymbolAddress((void**)&Woh, g_Woh);   cudaGetSymbolAddress((void**)&Wol, g_Wol);
    cudaGetSymbolAddress((void**)&Kth, g_Kth);   cudaGetSymbolAddress((void**)&Ktl, g_Ktl);
    cudaGetSymbolAddress((void**)&KVth, g_KVth); cudaGetSymbolAddress((void**)&KVtl, g_KVtl);
    cudaGetSymbolAddress((void**)&QtTh, g_QtTh); cudaGetSymbolAddress((void**)&QtTl, g_QtTl);
    cudaGetSymbolAddress((void**)&Ph,  g_Ph);    cudaGetSymbolAddress((void**)&Pl,  g_Pl);
    cudaGetSymbolAddress((void**)&Oh,  g_Oh);    cudaGetSymbolAddress((void**)&Ol,  g_Ol);
    cudaGetSymbolAddress((void**)&S,   g_S);
    cudaGetSymbolAddress((void**)&part, g_part);
    cudaGetSymbolAddress((void**)&stats, g_stats);

    const int  FULL = 0x7FFFFFFF;
    const float inv_scale = 1.0f / sqrtf(960.0f);
    const int  Cqs[4]   = {64, 128, 256, 512};
    const long qoff[4]  = {0, 524288, 1572864, 3670016};
    const long wqoff[4] = {0, 32768, 163840, 688128};
    const long wooff[4] = {0, 4096, 20480, 86016};

    // ---- converts (inputs -> bf16 hi/lo) ----
    cvt(KV, KVh, KVl, 7864320);
    cvt(Wk, Wkh, Wkl, 7372800);
    cvt(Wv, Wvh, Wvl, 7372800);
    for (int br = 0; br < 4; br++) {
        long Cq = Cqs[br];
        cvt(Q[br],  Qh + qoff[br],   Ql + qoff[br],   8192L * Cq);
        cvt(Wq[br], Wqh + wqoff[br], Wql + wqoff[br], 8L * Cq * Cq);
        cvt(Wo[br], Woh + wooff[br], Wol + wooff[br], Cq * Cq);
    }

    // ---- Kt = KV @ Wk^T  (bf16 hi/lo out) ----
    run_gemm(128, 1, dim3(15, 1, 64), KVh, KVl, Wkh, Wkl,
             nullptr, Kth, Ktl, nullptr,
             960, 960, 960, 960, 128L*960, FULL, 960L*960, 7, 128L*960, 1.f);
    // ---- KVt = Kt @ Wv^T ----
    run_gemm(128, 1, dim3(15, 1, 64), Kth, Ktl, Wvh, Wvl,
             nullptr, KVth, KVtl, nullptr,
             960, 960, 960, 960, 128L*960, FULL, 960L*960, 7, 128L*960, 1.f);
    // ---- KVtT [960][128] per batch (reuse dead Kt hi/lo buffers) ----
    __nv_bfloat16 *KVtTh = Kth, *KVtTl = Ktl;
    transpose_bf<<<dim3(30, 4, 64), dim3(32, 8)>>>(KVth, KVtl, KVtTh, KVtTl);

    long outOff = 0;
    for (int br = 0; br < 4; br++) {
        const int Cq = Cqs[br];
        const int BMq = (Cq >= 128) ? 128 : 64;
        // QtT[c,n] = sum_k Wq[c,k]*Q[n,k]
        run_gemm(BMq, 1, dim3(2, Cq / BMq, 64),
                 Wqh + wqoff[br], Wql + wqoff[br], Qh + qoff[br], Ql + qoff[br],
                 nullptr, QtTh, QtTl, nullptr,
                 Cq, Cq, Cq, 128, (long)Cq*Cq, 7, 128L*Cq, FULL, (long)Cq*128, 1.f);
        // S[c,s] = inv_scale * sum_n QtT[c,n]*KVtT[s,n]  (+ fused block stats partials)
        run_gemm(BMq, 2, dim3(15, Cq / BMq, 64),
                 QtTh, QtTl, KVtTh, KVtTl,
                 S, nullptr, nullptr, part,
                 128, 128, 128, 960, (long)Cq*128, FULL, 960L*128, FULL, (long)Cq*960, inv_scale);
        stats_fin<<<64, 64>>>(part, stats, 15 * (Cq / BMq), 1.0f / (float)(Cq * 960));
        inorm_softmax_bf<<<64 * Cq, 256>>>(S, stats, Ph, Pl, Cq);
        // O[n,c] = sum_s KVt[n,s]*P[c,s]  (bf16 hi/lo out, contiguous [B,N,Cq])
        run_gemm(128, 1, dim3(Cq / 64, 1, 64),
                 KVth, KVtl, Ph, Pl,
                 nullptr, Oh, Ol, nullptr,
                 960, 960, 960, Cq, 128L*960, FULL, (long)Cq*960, FULL, 128L*Cq, 1.f);
        // Y = O @ Wo^T  (fp32 out, M = B*N = 8192)
        run_gemm(128, 0, dim3(Cq / 64, 64, 1),
                 Oh, Ol, Woh + wooff[br], Wol + wooff[br],
                 out + outOff, nullptr, nullptr, nullptr,
                 Cq, Cq, Cq, Cq, 0, 0, 0, 0, 0, 1.f);
        outOff += 8192L * Cq;
    }
}

// round 11
// speedup vs baseline: 1.6223x; 1.6223x over previous
#include <cuda_runtime.h>
#include <cuda_bf16.h>
#include <math.h>
#include <stdint.h>

// ================= scratch (device globals: allocation-free) =================
__device__ float g_Kt [64u*128u*960u];   // Kt, then reused as KVtT [64][960][128]
__device__ float g_KVt[64u*128u*960u];   // KVt [64][128][960]
__device__ float g_QtT[64u*960u*128u];   // QtT concat: [64][mrow 960][128]
__device__ float g_S  [64u*960u*960u];   // S concat:  [64][mrow 960][960]  (236 MB)
__device__ float g_O  [8192u*960u];      // O concat:  [8192 tokens][ch 960]
__device__ float g_part[65536];          // per-(group,block) (sum,ss)
__device__ float g_stats[512];           // (mean,rstd) per group (256 groups)

// ================= per-branch GEMM params =================
struct GP {
    const float* A[4]; const float* B[4]; float* C[4];
    int  K[4], lda[4], ldb[4], ldc[4], aMask[4], bMask[4];
    long aS[4], bS[4], cS[4];
    float alpha[4];
    int cum0, cum1, cum2;      // cumulative tile thresholds for branch lookup
};

// ================= helpers =================
__device__ __forceinline__ void mma_bf16(float* c, const uint32_t* a, const uint32_t* b)
{
    asm volatile(
        "mma.sync.aligned.m16n8k16.row.col.f32.bf16.bf16.f32 "
        "{%0,%1,%2,%3}, {%4,%5,%6,%7}, {%8,%9}, {%0,%1,%2,%3};"
        : "+f"(c[0]), "+f"(c[1]), "+f"(c[2]), "+f"(c[3])
        : "r"(a[0]), "r"(a[1]), "r"(a[2]), "r"(a[3]), "r"(b[0]), "r"(b[1]));
}

__device__ __forceinline__ void split2(float x, float y, __nv_bfloat162& h, __nv_bfloat162& l)
{
    h.x = __float2bfloat16(x); h.y = __float2bfloat16(y);
    l.x = __float2bfloat16(x - __bfloat162float(h.x));
    l.y = __float2bfloat16(y - __bfloat162float(h.y));
}

// ================= merged NT GEMM, fp32 in/out, hi/lo split MMA =================
// C[m,n] = alpha * sum_k A[m,k]*B[n,k].  BM=BN=64, BK=32, 128 threads.
// AXIS 0: branch from blockIdx.y (M merged).  AXIS 1: branch from blockIdx.x (N merged).
// MODE 0: plain.  MODE 2: also emit per-block (sum,sumsq) partials for stats.
template<int AXIS, int MODE>
__global__ void __launch_bounds__(128)
gemm_mg(GP gp, float* __restrict__ part)
{
    constexpr int LDT = 40;
    __shared__ __nv_bfloat16 Ah[64][LDT], Al[64][LDT], Bh[64][LDT], Bl[64][LDT];

    const int t = (AXIS == 0) ? blockIdx.y : blockIdx.x;
    int br, tl;
    if      (t < gp.cum0) { br = 0; tl = t; }
    else if (t < gp.cum1) { br = 1; tl = t - gp.cum0; }
    else if (t < gp.cum2) { br = 2; tl = t - gp.cum1; }
    else                  { br = 3; tl = t - gp.cum2; }

    const float *A, *B; float* C;
    int K, lda, ldb, ldc, aM, bM; long aS, bS, cS; float alpha;
#define PICK(i) { A=gp.A[i]; B=gp.B[i]; C=gp.C[i]; K=gp.K[i]; lda=gp.lda[i]; ldb=gp.ldb[i]; \
                  ldc=gp.ldc[i]; aM=gp.aMask[i]; bM=gp.bMask[i]; aS=gp.aS[i]; bS=gp.bS[i]; \
                  cS=gp.cS[i]; alpha=gp.alpha[i]; }
    switch (br) { case 0: PICK(0); break; case 1: PICK(1); break;
                  case 2: PICK(2); break; default: PICK(3); break; }
#undef PICK

    const int z = blockIdx.z;
    A += (long)(z & aM) * aS;
    B += (long)(z & bM) * bS;
    C += (long)z * cS;

    const int m0 = (AXIS == 0 ? tl : (int)blockIdx.y) * 64;
    const int n0 = (AXIS == 0 ? (int)blockIdx.x : tl) * 64;
    const int tid = threadIdx.x, lane = tid & 31, warp = tid >> 5;
    const int wy = warp >> 1, wx = warp & 1;       // 2x2 warps, each 32x32
    const int m0w = wy * 32, n0w = wx * 32;
    const int r = lane >> 2, p = lane & 3;

    float acc[2][4][4];
#pragma unroll
    for (int mt = 0; mt < 2; mt++)
#pragma unroll
        for (int nt = 0; nt < 4; nt++)
#pragma unroll
            for (int i = 0; i < 4; i++) acc[mt][nt][i] = 0.f;

    for (int k0 = 0; k0 < K; k0 += 32) {
        // stage A (64x32 fp32 -> hi/lo bf16), 512 float4 over 128 threads
#pragma unroll
        for (int it = 0; it < 4; it++) {
            int idx = tid + it * 128;
            int kq = idx & 7, m = idx >> 3;
            float4 v = *reinterpret_cast<const float4*>(&A[(long)(m0 + m) * lda + k0 + kq * 4]);
            __nv_bfloat162 h0, l0, h1, l1;
            split2(v.x, v.y, h0, l0);
            split2(v.z, v.w, h1, l1);
            *reinterpret_cast<__nv_bfloat162*>(&Ah[m][kq * 4])     = h0;
            *reinterpret_cast<__nv_bfloat162*>(&Ah[m][kq * 4 + 2]) = h1;
            *reinterpret_cast<__nv_bfloat162*>(&Al[m][kq * 4])     = l0;
            *reinterpret_cast<__nv_bfloat162*>(&Al[m][kq * 4 + 2]) = l1;
        }
#pragma unroll
        for (int it = 0; it < 4; it++) {
            int idx = tid + it * 128;
            int kq = idx & 7, n = idx >> 3;
            float4 v = *reinterpret_cast<const float4*>(&B[(long)(n0 + n) * ldb + k0 + kq * 4]);
            __nv_bfloat162 h0, l0, h1, l1;
            split2(v.x, v.y, h0, l0);
            split2(v.z, v.w, h1, l1);
            *reinterpret_cast<__nv_bfloat162*>(&Bh[n][kq * 4])     = h0;
            *reinterpret_cast<__nv_bfloat162*>(&Bh[n][kq * 4 + 2]) = h1;
            *reinterpret_cast<__nv_bfloat162*>(&Bl[n][kq * 4])     = l0;
            *reinterpret_cast<__nv_bfloat162*>(&Bl[n][kq * 4 + 2]) = l1;
        }
        __syncthreads();

#pragma unroll
        for (int ks = 0; ks < 32; ks += 16) {
            const int kb = ks + 2 * p;
            uint32_t ah[2][4], al[2][4], bh[4][2], bl[4][2];
#pragma unroll
            for (int mt = 0; mt < 2; mt++) {
                int row = m0w + mt * 16 + r;
                ah[mt][0] = *(const uint32_t*)(&Ah[row][kb]);
                ah[mt][1] = *(const uint32_t*)(&Ah[row + 8][kb]);
                ah[mt][2] = *(const uint32_t*)(&Ah[row][kb + 8]);
                ah[mt][3] = *(const uint32_t*)(&Ah[row + 8][kb + 8]);
                al[mt][0] = *(const uint32_t*)(&Al[row][kb]);
                al[mt][1] = *(const uint32_t*)(&Al[row + 8][kb]);
                al[mt][2] = *(const uint32_t*)(&Al[row][kb + 8]);
                al[mt][3] = *(const uint32_t*)(&Al[row + 8][kb + 8]);
            }
#pragma unroll
            for (int nt = 0; nt < 4; nt++) {
                int row = n0w + nt * 8 + r;
                bh[nt][0] = *(const uint32_t*)(&Bh[row][kb]);
                bh[nt][1] = *(const uint32_t*)(&Bh[row][kb + 8]);
                bl[nt][0] = *(const uint32_t*)(&Bl[row][kb]);
                bl[nt][1] = *(const uint32_t*)(&Bl[row][kb + 8]);
            }
#pragma unroll
            for (int mt = 0; mt < 2; mt++)
#pragma unroll
                for (int nt = 0; nt < 4; nt++) {
                    mma_bf16(acc[mt][nt], ah[mt], bh[nt]);  // hi*hi
                    mma_bf16(acc[mt][nt], ah[mt], bl[nt]);  // hi*lo
                    mma_bf16(acc[mt][nt], al[mt], bh[nt]);  // lo*hi
                }
        }
        __syncthreads();
    }

    // ---- epilogue ----
    float sum = 0.f, ss = 0.f;
#pragma unroll
    for (int mt = 0; mt < 2; mt++) {
        int row = m0 + m0w + mt * 16 + r;
#pragma unroll
        for (int nt = 0; nt < 4; nt++) {
            int col = n0 + n0w + nt * 8 + 2 * p;
            float x0 = alpha * acc[mt][nt][0], y0 = alpha * acc[mt][nt][1];
            float x1 = alpha * acc[mt][nt][2], y1 = alpha * acc[mt][nt][3];
            *reinterpret_cast<float2*>(&C[(long)row * ldc + col])       = make_float2(x0, y0);
            *reinterpret_cast<float2*>(&C[(long)(row + 8) * ldc + col]) = make_float2(x1, y1);
            if (MODE == 2) {
                sum += x0 + y0 + x1 + y1;
                ss  += x0*x0 + y0*y0 + x1*x1 + y1*y1;
            }
        }
    }
    if (MODE == 2) {
#pragma unroll
        for (int o = 16; o; o >>= 1) {
            sum += __shfl_xor_sync(0xffffffffu, sum, o);
            ss  += __shfl_xor_sync(0xffffffffu, ss, o);
        }
        __shared__ float red[8];
        if (lane == 0) { red[warp] = sum; red[4 + warp] = ss; }
        __syncthreads();
        if (tid == 0) {
            float s1 = red[0] + red[1] + red[2] + red[3];
            float s2 = red[4] + red[5] + red[6] + red[7];
            int g  = br * 64 + z;                       // group = (branch, bh)
            int bz = tl * gridDim.x + blockIdx.x;       // local block id within group (<120)
            part[((long)g * 128 + bz) * 2 + 0] = s1;
            part[((long)g * 128 + bz) * 2 + 1] = s2;
        }
    }
}

// ================= stats finalize: 256 groups, deterministic =================
__global__ void stats_fin(const float* __restrict__ part, float* __restrict__ stats)
{
    const int g = blockIdx.x;          // 0..255
    const int br = g >> 6;
    const int nbTab[4]  = {15, 30, 60, 120};
    const float ivTab[4] = {1.f/(64*960.f), 1.f/(128*960.f), 1.f/(256*960.f), 1.f/(512*960.f)};
    const int nb = nbTab[br];
    const int tid = threadIdx.x;
    __shared__ float s1[128], s2[128];
    float a = 0.f, b = 0.f;
    for (int i = tid; i < nb; i += 128) {
        a += part[((long)g * 128 + i) * 2 + 0];
        b += part[((long)g * 128 + i) * 2 + 1];
    }
    s1[tid] = a; s2[tid] = b; __syncthreads();
    for (int o = 64; o; o >>= 1) {
        if (tid < o) { s1[tid] += s1[tid + o]; s2[tid] += s2[tid + o]; }
        __syncthreads();
    }
    if (tid == 0) {
        float m = s1[0] * ivTab[br];
        float v = s2[0] * ivTab[br] - m * m;
        stats[2 * g]     = m;
        stats[2 * g + 1] = rsqrtf(v + 1e-5f);
    }
}

// ================= merged inorm apply + softmax over 960 (in place, fp32) =====
__global__ void inorm_softmax_all(float* __restrict__ S, const float* __restrict__ stats)
{
    const int row = blockIdx.x;              // 0..61439 = z*960 + mrow
    const int z = row / 960, mr = row - z * 960;
    const int br = (mr < 64) ? 0 : (mr < 192) ? 1 : (mr < 448) ? 2 : 3;
    const int g = br * 64 + z;
    float* p = S + (long)row * 960;
    const int tid = threadIdx.x;             // 256 threads, 240 active
    const bool act = tid < 240;
    const float mean = stats[2 * g], rstd = stats[2 * g + 1];

    float4 v = make_float4(0.f, 0.f, 0.f, 0.f);
    if (act) v = *reinterpret_cast<float4*>(&p[tid * 4]);
    v.x = (v.x - mean) * rstd; v.y = (v.y - mean) * rstd;
    v.z = (v.z - mean) * rstd; v.w = (v.w - mean) * rstd;

    __shared__ float sh[256];
    float mx = act ? fmaxf(fmaxf(v.x, v.y), fmaxf(v.z, v.w)) : -1e30f;
    sh[tid] = mx; __syncthreads();
    for (int o = 128; o > 0; o >>= 1) {
        if (tid < o) sh[tid] = fmaxf(sh[tid], sh[tid + o]);
        __syncthreads();
    }
    mx = sh[0]; __syncthreads();

    float4 e;
    e.x = __expf(v.x - mx); e.y = __expf(v.y - mx);
    e.z = __expf(v.z - mx); e.w = __expf(v.w - mx);
    float s = act ? (e.x + e.y + e.z + e.w) : 0.f;
    sh[tid] = s; __syncthreads();
    for (int o = 128; o > 0; o >>= 1) {
        if (tid < o) sh[tid] += sh[tid + o];
        __syncthreads();
    }
    const float inv = 1.f / sh[0];
    if (act) {
        e.x *= inv; e.y *= inv; e.z *= inv; e.w *= inv;
        *reinterpret_cast<float4*>(&p[tid * 4]) = e;
    }
}

// ================= transpose: [z][128][960] -> [z][960][128], fp32 =================
__global__ void transpose_kvt(const float* __restrict__ in, float* __restrict__ out)
{
    __shared__ float t[32][33];
    const int b = blockIdx.z;
    const int s0 = blockIdx.x * 32, n0 = blockIdx.y * 32;
    in  += (long)b * 128 * 960;
    out += (long)b * 960 * 128;
    const int tx = threadIdx.x, ty = threadIdx.y;
#pragma unroll
    for (int i = 0; i < 4; i++)
        t[ty + 8 * i][tx] = in[(long)(n0 + ty + 8 * i) * 960 + s0 + tx];
    __syncthreads();
#pragma unroll
    for (int i = 0; i < 4; i++)
        out[(long)(s0 + ty + 8 * i) * 128 + n0 + tx] = t[tx][ty + 8 * i];
}

// ================= host side =================
extern "C" void kernel_launch(void* const* d_in, const int* in_sizes, int n_in,
                              void* d_out, int out_size)
{
    const float* Q[4]  = {(const float*)d_in[0], (const float*)d_in[1],
                          (const float*)d_in[2], (const float*)d_in[3]};
    const float* KV    = (const float*)d_in[4];
    const float* Wk    = (const float*)d_in[5];
    const float* Wv    = (const float*)d_in[6];
    const float* Wq[4] = {(const float*)d_in[7], (const float*)d_in[8],
                          (const float*)d_in[9], (const float*)d_in[10]};
    const float* Wo[4] = {(const float*)d_in[11], (const float*)d_in[12],
                          (const float*)d_in[13], (const float*)d_in[14]};
    float* out = (float*)d_out;

    float *Kt, *KVt, *QtT, *S, *O, *part, *stats;
    cudaGetSymbolAddress((void**)&Kt,   g_Kt);
    cudaGetSymbolAddress((void**)&KVt,  g_KVt);
    cudaGetSymbolAddress((void**)&QtT,  g_QtT);
    cudaGetSymbolAddress((void**)&S,    g_S);
    cudaGetSymbolAddress((void**)&O,    g_O);
    cudaGetSymbolAddress((void**)&part, g_part);
    cudaGetSymbolAddress((void**)&stats,g_stats);

    const int FULL = 0x7FFFFFFF;
    const float inv_scale = 1.0f / sqrtf(960.0f);
    const int Cq[4]   = {64, 128, 256, 512};
    const int moff[4] = {0, 64, 192, 448};   // concat row offsets (sum = 960)

    GP gp;

    // ---- 1) Kt = KV @ Wk^T : single-branch via merged kernel (all blocks br=0) ----
    for (int i = 0; i < 4; i++) {
        gp.A[i] = KV;  gp.B[i] = Wk;  gp.C[i] = Kt;
        gp.K[i] = 960; gp.lda[i] = 960; gp.ldb[i] = 960; gp.ldc[i] = 960;
        gp.aMask[i] = FULL; gp.bMask[i] = 7;
        gp.aS[i] = 128L*960; gp.bS[i] = 960L*960; gp.cS[i] = 128L*960;
        gp.alpha[i] = 1.f;
    }
    gp.cum0 = 1000; gp.cum1 = 1001; gp.cum2 = 1002;
    gemm_mg<0,0><<<dim3(15, 2, 64), 128>>>(gp, part);

    // ---- 2) KVt = Kt @ Wv^T ----
    for (int i = 0; i < 4; i++) { gp.A[i] = Kt; gp.B[i] = Wv; gp.C[i] = KVt; }
    gemm_mg<0,0><<<dim3(15, 2, 64), 128>>>(gp, part);

    // ---- 3) KVtT [z][960][128] (reuse Kt) ----
    float* KVtT = Kt;
    transpose_kvt<<<dim3(30, 4, 64), dim3(32, 8)>>>(KVt, KVtT);

    // ---- 4) QtT merged: QtT[c,n] = sum_k Wq[c,k] * Q[n,k]  (M=Cq merged on y) ----
    for (int i = 0; i < 4; i++) {
        gp.A[i] = Wq[i];          gp.B[i] = Q[i];           gp.C[i] = QtT + (long)moff[i] * 128;
        gp.K[i] = Cq[i];          gp.lda[i] = Cq[i];        gp.ldb[i] = Cq[i];  gp.ldc[i] = 128;
        gp.aMask[i] = 7;          gp.bMask[i] = FULL;
        gp.aS[i] = (long)Cq[i]*Cq[i]; gp.bS[i] = 128L*Cq[i]; gp.cS[i] = 960L*128;
        gp.alpha[i] = 1.f;
    }
    gp.cum0 = 1; gp.cum1 = 3; gp.cum2 = 7;   // m-tiles {1,2,4,8}
    gemm_mg<0,0><<<dim3(2, 15, 64), 128>>>(gp, part);

    // ---- 5) S merged: S[c,s] = inv_scale * sum_n QtT[c,n]*KVtT[s,n]  (+ stats partials) ----
    for (int i = 0; i < 4; i++) {
        gp.A[i] = QtT + (long)moff[i] * 128;  gp.B[i] = KVtT;  gp.C[i] = S + (long)moff[i] * 960;
        gp.K[i] = 128;  gp.lda[i] = 128; gp.ldb[i] = 128; gp.ldc[i] = 960;
        gp.aMask[i] = FULL; gp.bMask[i] = FULL;
        gp.aS[i] = 960L*128; gp.bS[i] = 960L*128; gp.cS[i] = 960L*960;
        gp.alpha[i] = inv_scale;
    }
    gp.cum0 = 1; gp.cum1 = 3; gp.cum2 = 7;
    gemm_mg<0,2><<<dim3(15, 15, 64), 128>>>(gp, part);

    // ---- 6) stats + 7) softmax (merged, in place) ----
    stats_fin<<<256, 128>>>(part, stats);
    inorm_softmax_all<<<61440, 256>>>(S, stats);

    // ---- 8) O merged: O[n,c] = sum_s KVt[n,s]*P[c,s]  (N=Cq merged on x) ----
    for (int i = 0; i < 4; i++) {
        gp.A[i] = KVt;  gp.B[i] = S + (long)moff[i] * 960;  gp.C[i] = O + moff[i];
        gp.K[i] = 960;  gp.lda[i] = 960; gp.ldb[i] = 960;   gp.ldc[i] = 960;
        gp.aMask[i] = FULL; gp.bMask[i] = FULL;
        gp.aS[i] = 128L*960; gp.bS[i] = 960L*960; gp.cS[i] = 128L*960;
        gp.alpha[i] = 1.f;
    }
    gp.cum0 = 1; gp.cum1 = 3; gp.cum2 = 7;   // n-tiles {1,2,4,8}
    gemm_mg<1,0><<<dim3(15, 2, 64), 128>>>(gp, part);

    // ---- 9) Wo merged: Y = O @ Wo^T  (N=Cq merged on x, M=8192) ----
    for (int i = 0; i < 4; i++) {
        gp.A[i] = O + moff[i];  gp.B[i] = Wo[i];  gp.C[i] = out + 8192L * moff[i];
        gp.K[i] = Cq[i];  gp.lda[i] = 960; gp.ldb[i] = Cq[i]; gp.ldc[i] = Cq[i];
        gp.aMask[i] = 0; gp.bMask[i] = 0;
        gp.aS[i] = 0; gp.bS[i] = 0; gp.cS[i] = 0;
        gp.alpha[i] = 1.f;
    }
    gp.cum0 = 1; gp.cum1 = 3; gp.cum2 = 7;
    gemm_mg<1,0><<<dim3(15, 128, 1), 128>>>(gp, part);
}